// round 15
// baseline (speedup 1.0000x reference)
#include <cuda_runtime.h>
#include <cstdint>

#define NROWS 8191
#define C2    0.011271055006945017f    /* 2*gamma*log2(e), gamma=1/256 */
#define NGL2  0.0056355275034725085f   /* gamma*log2(e) */

// ---------------- device scratch (no allocation allowed) ----------------
__device__ float g_yt[8192 * 128];   // tf32 yt keys, dims permuted within 8
__device__ float g_vt[128 * 8192];   // tf32 V transposed [dim][key], keys permuted within 8
__device__ float g_cq[8192];         // -gamma*log2e*||x_i||^2
__device__ float g_ck[8192];         // -gamma*log2e*||yt_j||^2 ; row 8191 -> -1e30
__device__ float g_op[4 * 8192 * 128]; // split-K partial O planes (unnormalized)
__device__ float g_dp[4 * 8192];       // split-K partial denominators

__device__ __host__ __forceinline__ int sperm(int k) { return ((k & 3) << 1) | (k >> 2); }

__device__ __forceinline__ float tf32r(float x) {
    uint32_t u; asm("cvt.rna.tf32.f32 %0, %1;" : "=r"(u) : "f"(x));
    return __uint_as_float(u);
}
__device__ __forceinline__ float ex2f(float x) {
    float r; asm("ex2.approx.f32 %0, %1;" : "=f"(r) : "f"(x)); return r;
}
__device__ __forceinline__ uint32_t smaddr(const void* p) {
    uint32_t a;
    asm("{ .reg .u64 t; cvta.to.shared.u64 t, %1; cvt.u32.u64 %0, t; }" : "=r"(a) : "l"(p));
    return a;
}
#define CP16(dst, src) \
    asm volatile("cp.async.cg.shared.global [%0], [%1], 16;" \
                 :: "r"(dst), "l"((size_t)__cvta_generic_to_global(src)) : "memory")
#define CP_COMMIT() asm volatile("cp.async.commit_group;" ::: "memory")
#define CP_WAIT0()  asm volatile("cp.async.wait_group 0;" ::: "memory")

__device__ __forceinline__ void mma8(float* c, uint32_t a0, uint32_t a1, uint32_t a2,
                                     uint32_t a3, uint32_t b0, uint32_t b1) {
    asm volatile("mma.sync.aligned.m16n8k8.row.col.f32.tf32.tf32.f32 "
                 "{%0,%1,%2,%3}, {%4,%5,%6,%7}, {%8,%9}, {%0,%1,%2,%3};"
                 : "+f"(c[0]), "+f"(c[1]), "+f"(c[2]), "+f"(c[3])
                 : "r"(a0), "r"(a1), "r"(a2), "r"(a3), "r"(b0), "r"(b1));
}

// ---------------- kernel 1: yt = y @ R^T + t (tf32, dims permuted) ---------
__global__ __launch_bounds__(256) void yt_kernel(const float* __restrict__ y,
                                                 const float* __restrict__ R,
                                                 const float* __restrict__ t)
{
    extern __shared__ char smem[];
    float* yT = (float*)smem;
    float* RT = (float*)(smem + 34816);
    const int tid = threadIdx.x;
    const int r0  = blockIdx.x * 64;

    #pragma unroll
    for (int s = 0; s < 32; s++) {
        int e = tid + s * 256, row = e >> 7, k = e & 127, gr = r0 + row;
        yT[k * 68 + row] = (gr < NROWS) ? y[gr * 128 + k] : 0.0f;
    }
    #pragma unroll
    for (int s = 0; s < 64; s++) {
        int e = tid + s * 256, c = e >> 7, k = e & 127;
        RT[k * 132 + c] = R[e];
    }
    __syncthreads();

    const int tr = tid >> 4, tc = tid & 15;
    float acc[4][8];
    #pragma unroll
    for (int i = 0; i < 4; i++)
        #pragma unroll
        for (int j = 0; j < 8; j++) acc[i][j] = 0.0f;

    const float4* yT4 = (const float4*)yT;
    const float4* RT4 = (const float4*)RT;
    #pragma unroll 8
    for (int k = 0; k < 128; k++) {
        float4 a  = yT4[k * 17 + tr];
        float4 b0 = RT4[k * 33 + tc * 2];
        float4 b1 = RT4[k * 33 + tc * 2 + 1];
        float av[4] = {a.x, a.y, a.z, a.w};
        float bv[8] = {b0.x, b0.y, b0.z, b0.w, b1.x, b1.y, b1.z, b1.w};
        #pragma unroll
        for (int i = 0; i < 4; i++)
            #pragma unroll
            for (int j = 0; j < 8; j++) acc[i][j] += av[i] * bv[j];
    }
    float tv[8];
    #pragma unroll
    for (int j = 0; j < 8; j++) tv[j] = t[tc * 8 + j];
    #pragma unroll
    for (int i = 0; i < 4; i++) {
        int row = r0 + tr * 4 + i;
        #pragma unroll
        for (int j = 0; j < 8; j++)
            g_yt[row * 128 + tc * 8 + sperm(j)] = tf32r(acc[i][j] + tv[j]);
    }
}

// ---------------- kernel 2: scaled norms ----------------
__global__ __launch_bounds__(128) void norm_kernel(const float* __restrict__ X)
{
    const int row = blockIdx.x, which = blockIdx.y;
    float v = which ? g_yt[row * 128 + threadIdx.x]
                    : tf32r(X[row * 128 + threadIdx.x]);
    float s = v * v;
    #pragma unroll
    for (int o = 16; o; o >>= 1) s += __shfl_down_sync(0xFFFFFFFFu, s, o);
    __shared__ float red[4];
    if ((threadIdx.x & 31) == 0) red[threadIdx.x >> 5] = s;
    __syncthreads();
    if (threadIdx.x == 0) {
        float tot = -(red[0] + red[1] + red[2] + red[3]) * NGL2;
        if (which) g_ck[row] = (row < NROWS) ? tot : -1e30f;
        else       g_cq[row] = tot;
    }
}

// ---------------- kernel 3: V transpose [dim][key], keys permuted ----------
__global__ __launch_bounds__(256) void vt_kernel(const float* __restrict__ X)
{
    __shared__ float ts[64 * 133];
    const int tid = threadIdx.x;
    const int j0 = blockIdx.x * 64;

    #pragma unroll
    for (int i = 0; i < 8; i++) {
        int f = tid + i * 256;
        int r = f >> 5, c4 = f & 31;
        int src = j0 + r + 1; if (src > 8191) src = 8191;
        float4 v = ((const float4*)X)[(size_t)src * 32 + c4];
        float* d = &ts[r * 133 + c4 * 4];
        d[0] = v.x; d[1] = v.y; d[2] = v.z; d[3] = v.w;
    }
    __syncthreads();

    const int w = tid >> 5, l = tid & 31;
    #pragma unroll
    for (int db = 0; db < 16; db++) {
        int d = db * 8 + w;
        #pragma unroll
        for (int it = 0; it < 2; it++) {
            int r = it * 32 + l;
            int jst = (r & ~7) | sperm(r & 7);
            g_vt[(size_t)d * 8192 + j0 + jst] = tf32r(ts[r * 133 + d]);
        }
    }
}

// ---------------- kernel 4: flash RBF attention, split-K over 4 planes -----
// grid (128, 4): blockIdx.x = query tile (64 rows), blockIdx.y = key split s
// (key tiles [32s, 32s+32)). Writes unnormalized O to g_op plane s + den to g_dp.
#define SQ 136
#define SVD 72
#define QSO 0
#define KSO(b)  (8704 + (b) * 8704)
#define VSO(b)  (26112 + (b) * 9216)
#define PSO(pb) (44544 + (pb) * 4608)
#define CKO(b)  (53760 + (b) * 64)
#define DNO 53888
#define SMEM_BYTES (54144 * 4)

__global__ __launch_bounds__(512, 1) void attn_kernel(const float* __restrict__ X)
{
    extern __shared__ float sm[];
    const int tid = threadIdx.x;
    const int w = tid >> 5, l = tid & 31;
    const int gid = l >> 2, tig = l & 3;
    const int wm = w >> 2, q = w & 3;
    const int hm = wm >> 1, kv = q >> 1, nq = ((wm & 1) << 1) | (q & 1);
    const int mb = wm * 16;
    const int mb2 = hm * 32;
    const int nb2 = nq * 32;
    const int barid = 1 + hm * 2 + kv;
    const int r0 = blockIdx.x * 64;
    const int sp = blockIdx.y;               // key split 0..3
    const int t0 = sp * 32;                  // first key tile of this split
    const int s0 = ((tig & 1) << 2) | (tig >> 1);

    {
        const float4* X4 = (const float4*)X;
        #pragma unroll
        for (int i = 0; i < 4; i++) {
            int f = tid + i * 512, r = f >> 5, c4 = f & 31;
            float4 qv = X4[(size_t)(r0 + r) * 32 + c4];
            int base = QSO + r * SQ + (c4 >> 1) * 8 + (c4 & 1);
            sm[base + 0] = tf32r(qv.x); sm[base + 2] = tf32r(qv.y);
            sm[base + 4] = tf32r(qv.z); sm[base + 6] = tf32r(qv.w);
        }
    }
    const float cq0 = g_cq[r0 + mb + gid];
    const float cq1 = g_cq[r0 + mb + gid + 8];

    // prime first tile of this split -> buf 0
    {
        const int j0 = t0 * 64;
        #pragma unroll
        for (int i = 0; i < 4; i++) {
            int f = tid + i * 512, r = f >> 5, c4 = f & 31;
            CP16(smaddr(&sm[KSO(0) + r * SQ + c4 * 4]),
                 g_yt + (size_t)(j0 + r) * 128 + c4 * 4);
        }
        #pragma unroll
        for (int i = 0; i < 4; i++) {
            int f = tid + i * 512, d = f >> 4, c = f & 15;
            CP16(smaddr(&sm[VSO(0) + d * SVD + c * 4]),
                 g_vt + (size_t)d * 8192 + j0 + c * 4);
        }
        if (tid < 16) CP16(smaddr(&sm[CKO(0) + tid * 4]), g_ck + j0 + tid * 4);
        CP_COMMIT();
    }

    float oa[2][4][4];
    #pragma unroll
    for (int m = 0; m < 2; m++)
        #pragma unroll
        for (int n = 0; n < 4; n++)
            #pragma unroll
            for (int j = 0; j < 4; j++) oa[m][n][j] = 0.0f;
    float dn0 = 0.0f, dn1 = 0.0f;

    const int qA0 = (mb + gid) * SQ + 2 * tig;
    const int qA1 = (mb + gid + 8) * SQ + 2 * tig;
    const int kB0 = (q * 16 + gid) * SQ + 2 * tig;
    const int pA0 = (mb2 + gid) * SVD;
    const int vB0 = (nb2 + gid) * SVD;

    #pragma unroll 1
    for (int tt = 0; tt < 32; tt++) {
        const int b = tt & 1;

        CP_WAIT0();
        __syncthreads();

        if (tt + 1 < 32) {
            const int nb = b ^ 1;
            const int j0 = (t0 + tt + 1) * 64;
            #pragma unroll
            for (int i = 0; i < 4; i++) {
                int f = tid + i * 512, r = f >> 5, c4 = f & 31;
                CP16(smaddr(&sm[KSO(nb) + r * SQ + c4 * 4]),
                     g_yt + (size_t)(j0 + r) * 128 + c4 * 4);
            }
            #pragma unroll
            for (int i = 0; i < 4; i++) {
                int f = tid + i * 512, d = f >> 4, c = f & 15;
                CP16(smaddr(&sm[VSO(nb) + d * SVD + c * 4]),
                     g_vt + (size_t)d * 8192 + j0 + c * 4);
            }
            if (tid < 16) CP16(smaddr(&sm[CKO(nb) + tid * 4]), g_ck + j0 + tid * 4);
            CP_COMMIT();
        }

        float sa[2][4];
        #pragma unroll
        for (int n = 0; n < 2; n++)
            #pragma unroll
            for (int j = 0; j < 4; j++) sa[n][j] = 0.0f;

        const uint32_t* QsU = (const uint32_t*)&sm[QSO];
        const uint32_t* KsU = (const uint32_t*)&sm[KSO(b)];
        #pragma unroll
        for (int k0 = 0; k0 < 16; k0++) {
            uint2 aA = *(const uint2*)&QsU[qA0 + k0 * 8];
            uint2 aB = *(const uint2*)&QsU[qA1 + k0 * 8];
            #pragma unroll
            for (int n0 = 0; n0 < 2; n0++) {
                uint2 bb = *(const uint2*)&KsU[kB0 + n0 * 8 * SQ + k0 * 8];
                mma8(sa[n0], aA.x, aB.x, aA.y, aB.y, bb.x, bb.y);
            }
        }

        const float* ckb = &sm[CKO(b)];
        float* Ps = &sm[PSO(b)];
        #pragma unroll
        for (int n0 = 0; n0 < 2; n0++) {
            int cl = q * 16 + n0 * 8;
            float ck0 = ckb[cl + 2 * tig], ck1 = ckb[cl + 2 * tig + 1];
            float p0 = tf32r(ex2f(fmaf(C2, sa[n0][0], cq0 + ck0)));
            float p1 = tf32r(ex2f(fmaf(C2, sa[n0][1], cq0 + ck1)));
            float p2 = tf32r(ex2f(fmaf(C2, sa[n0][2], cq1 + ck0)));
            float p3 = tf32r(ex2f(fmaf(C2, sa[n0][3], cq1 + ck1)));
            dn0 += p0 + p1;
            dn1 += p2 + p3;
            int rA = mb + gid, rB = rA + 8;
            Ps[rA * SVD + cl + s0]     = p0;
            Ps[rA * SVD + cl + s0 + 2] = p1;
            Ps[rB * SVD + cl + s0]     = p2;
            Ps[rB * SVD + cl + s0 + 2] = p3;
        }
        asm volatile("bar.sync %0, %1;" :: "r"(barid), "r"(128) : "memory");

        const uint32_t* PsU = (const uint32_t*)&sm[PSO(b)];
        const uint32_t* VsU = (const uint32_t*)&sm[VSO(b)];
        #pragma unroll
        for (int k0 = 0; k0 < 4; k0++) {
            int kc = kv * 32 + k0 * 8 + 2 * tig;
            uint2 p0 = *(const uint2*)&PsU[pA0 + kc];
            uint2 p1 = *(const uint2*)&PsU[pA0 + 8 * SVD + kc];
            uint2 p2 = *(const uint2*)&PsU[pA0 + 16 * SVD + kc];
            uint2 p3 = *(const uint2*)&PsU[pA0 + 24 * SVD + kc];
            #pragma unroll
            for (int n0 = 0; n0 < 4; n0++) {
                uint2 vb = *(const uint2*)&VsU[vB0 + n0 * 8 * SVD + kc];
                mma8(oa[0][n0], p0.x, p1.x, p0.y, p1.y, vb.x, vb.y);
                mma8(oa[1][n0], p2.x, p3.x, p2.y, p3.y, vb.x, vb.y);
            }
        }
    }

    // ---- epilogue: den quarters -> smem; kv=1 warps park partial O ----
    dn0 += __shfl_xor_sync(0xFFFFFFFFu, dn0, 1);
    dn0 += __shfl_xor_sync(0xFFFFFFFFu, dn0, 2);
    dn1 += __shfl_xor_sync(0xFFFFFFFFu, dn1, 1);
    dn1 += __shfl_xor_sync(0xFFFFFFFFu, dn1, 2);
    if (tig == 0) {
        sm[DNO + q * 64 + mb + gid]     = dn0;
        sm[DNO + q * 64 + mb + gid + 8] = dn1;
    }
    if (kv) {
        float* ob = &sm[VSO(0)];
        #pragma unroll
        for (int m = 0; m < 2; m++) {
            int rA = mb2 + gid + 16 * m, rB = rA + 8;
            #pragma unroll
            for (int n0 = 0; n0 < 4; n0++) {
                int col = nb2 + n0 * 8 + 2 * tig;
                *(float2*)&ob[rA * 132 + col] = make_float2(oa[m][n0][0], oa[m][n0][1]);
                *(float2*)&ob[rB * 132 + col] = make_float2(oa[m][n0][2], oa[m][n0][3]);
            }
        }
    }
    __syncthreads();

    if (!kv) {                               // CTA-level sum -> plane sp (unnormalized)
        float* op = g_op + (size_t)sp * (8192 * 128);
        float* dp = g_dp + sp * 8192;
        const float* ob = &sm[VSO(0)];
        #pragma unroll
        for (int m = 0; m < 2; m++) {
            int rA = mb2 + gid + 16 * m, rB = rA + 8;
            float dA = sm[DNO + rA] + sm[DNO + 64 + rA] + sm[DNO + 128 + rA] + sm[DNO + 192 + rA];
            float dB = sm[DNO + rB] + sm[DNO + 64 + rB] + sm[DNO + 128 + rB] + sm[DNO + 192 + rB];
            int gA = r0 + rA, gB = r0 + rB;
            if (tig == 0 && nq == 0) { dp[gA] = dA; dp[gB] = dB; }
            #pragma unroll
            for (int n0 = 0; n0 < 4; n0++) {
                int col = nb2 + n0 * 8 + 2 * tig;
                float2 uA = *(const float2*)&ob[rA * 132 + col];
                float2 uB = *(const float2*)&ob[rB * 132 + col];
                *(float2*)&op[(size_t)gA * 128 + col] =
                    make_float2(oa[m][n0][0] + uA.x, oa[m][n0][1] + uA.y);
                *(float2*)&op[(size_t)gB * 128 + col] =
                    make_float2(oa[m][n0][2] + uB.x, oa[m][n0][3] + uB.y);
            }
        }
    }
}

// ---------------- kernel 5: combine 4 planes + normalize -------------------
__global__ __launch_bounds__(256) void reduce_kernel(float* __restrict__ out)
{
    int f = blockIdx.x * 256 + threadIdx.x;     // float4 index over 8192*32
    int row = f >> 5, c4 = f & 31;
    if (row >= NROWS) return;
    const float4* p0 = (const float4*)g_op;
    float4 a = p0[(size_t)row * 32 + c4];
    float4 b = p0[(size_t)(8192 * 32) + row * 32 + c4];
    float4 c = p0[(size_t)(2 * 8192 * 32) + row * 32 + c4];
    float4 d = p0[(size_t)(3 * 8192 * 32) + row * 32 + c4];
    float den = g_dp[row] + g_dp[8192 + row] + g_dp[16384 + row] + g_dp[24576 + row];
    float inv = 1.0f / den;
    float4 o;
    o.x = (a.x + b.x + c.x + d.x) * inv;
    o.y = (a.y + b.y + c.y + d.y) * inv;
    o.z = (a.z + b.z + c.z + d.z) * inv;
    o.w = (a.w + b.w + c.w + d.w) * inv;
    ((float4*)out)[(size_t)row * 32 + c4] = o;
}

// ---------------- launch ----------------------------------------------------
extern "C" void kernel_launch(void* const* d_in, const int* in_sizes, int n_in,
                              void* d_out, int out_size)
{
    const float* X = (const float*)d_in[0];
    const float* y = (const float*)d_in[1];
    const float* R = (const float*)d_in[3];
    const float* t = (const float*)d_in[4];
    float* out = (float*)d_out;

    cudaFuncSetAttribute(yt_kernel,   cudaFuncAttributeMaxDynamicSharedMemorySize, 102400);
    cudaFuncSetAttribute(attn_kernel, cudaFuncAttributeMaxDynamicSharedMemorySize, SMEM_BYTES);

    yt_kernel<<<128, 256, 102400>>>(y, R, t);
    norm_kernel<<<dim3(8192, 2), 128>>>(X);
    vt_kernel<<<128, 256>>>(X);
    attn_kernel<<<dim3(128, 4), 512, SMEM_BYTES>>>(X);
    reduce_kernel<<<1024, 256>>>(out);
}

// round 17
// speedup vs baseline: 1.0940x; 1.0940x over previous
#include <cuda_runtime.h>
#include <cstdint>

#define NROWS 8191
#define C2    0.011271055006945017f    /* 2*gamma*log2(e), gamma=1/256 */
#define NGL2  0.0056355275034725085f   /* gamma*log2(e) */
#define NSPLIT 8

// ---------------- device scratch (no allocation allowed) ----------------
__device__ float g_yt[8192 * 128];   // tf32 yt keys, dims permuted within 8
__device__ float g_vt[128 * 8192];   // tf32 V transposed [dim][key], keys permuted within 8
__device__ float g_cq[8192];         // -gamma*log2e*||x_i||^2
__device__ float g_ck[8192];         // -gamma*log2e*||yt_j||^2 ; row 8191 -> -1e30
__device__ float g_op[NSPLIT * 8192 * 128]; // split-K partial O planes (unnormalized)
__device__ float g_dp[NSPLIT * 8192];       // split-K partial denominators

__device__ __host__ __forceinline__ int sperm(int k) { return ((k & 3) << 1) | (k >> 2); }

__device__ __forceinline__ float tf32r(float x) {
    uint32_t u; asm("cvt.rna.tf32.f32 %0, %1;" : "=r"(u) : "f"(x));
    return __uint_as_float(u);
}
__device__ __forceinline__ float ex2f(float x) {
    float r; asm("ex2.approx.f32 %0, %1;" : "=f"(r) : "f"(x)); return r;
}
__device__ __forceinline__ uint32_t smaddr(const void* p) {
    uint32_t a;
    asm("{ .reg .u64 t; cvta.to.shared.u64 t, %1; cvt.u32.u64 %0, t; }" : "=r"(a) : "l"(p));
    return a;
}
#define CP16(dst, src) \
    asm volatile("cp.async.cg.shared.global [%0], [%1], 16;" \
                 :: "r"(dst), "l"((size_t)__cvta_generic_to_global(src)) : "memory")
#define CP_COMMIT() asm volatile("cp.async.commit_group;" ::: "memory")
#define CP_WAIT0()  asm volatile("cp.async.wait_group 0;" ::: "memory")

__device__ __forceinline__ void mma8(float* c, uint32_t a0, uint32_t a1, uint32_t a2,
                                     uint32_t a3, uint32_t b0, uint32_t b1) {
    asm volatile("mma.sync.aligned.m16n8k8.row.col.f32.tf32.tf32.f32 "
                 "{%0,%1,%2,%3}, {%4,%5,%6,%7}, {%8,%9}, {%0,%1,%2,%3};"
                 : "+f"(c[0]), "+f"(c[1]), "+f"(c[2]), "+f"(c[3])
                 : "r"(a0), "r"(a1), "r"(a2), "r"(a3), "r"(b0), "r"(b1));
}

// ---------------- kernel 1: yt = y @ R^T + t (tf32, dims permuted) ---------
__global__ __launch_bounds__(256) void yt_kernel(const float* __restrict__ y,
                                                 const float* __restrict__ R,
                                                 const float* __restrict__ t)
{
    extern __shared__ char smem[];
    float* yT = (float*)smem;
    float* RT = (float*)(smem + 34816);
    const int tid = threadIdx.x;
    const int r0  = blockIdx.x * 64;

    #pragma unroll
    for (int s = 0; s < 32; s++) {
        int e = tid + s * 256, row = e >> 7, k = e & 127, gr = r0 + row;
        yT[k * 68 + row] = (gr < NROWS) ? y[gr * 128 + k] : 0.0f;
    }
    #pragma unroll
    for (int s = 0; s < 64; s++) {
        int e = tid + s * 256, c = e >> 7, k = e & 127;
        RT[k * 132 + c] = R[e];
    }
    __syncthreads();

    const int tr = tid >> 4, tc = tid & 15;
    float acc[4][8];
    #pragma unroll
    for (int i = 0; i < 4; i++)
        #pragma unroll
        for (int j = 0; j < 8; j++) acc[i][j] = 0.0f;

    const float4* yT4 = (const float4*)yT;
    const float4* RT4 = (const float4*)RT;
    #pragma unroll 8
    for (int k = 0; k < 128; k++) {
        float4 a  = yT4[k * 17 + tr];
        float4 b0 = RT4[k * 33 + tc * 2];
        float4 b1 = RT4[k * 33 + tc * 2 + 1];
        float av[4] = {a.x, a.y, a.z, a.w};
        float bv[8] = {b0.x, b0.y, b0.z, b0.w, b1.x, b1.y, b1.z, b1.w};
        #pragma unroll
        for (int i = 0; i < 4; i++)
            #pragma unroll
            for (int j = 0; j < 8; j++) acc[i][j] += av[i] * bv[j];
    }
    float tv[8];
    #pragma unroll
    for (int j = 0; j < 8; j++) tv[j] = t[tc * 8 + j];
    #pragma unroll
    for (int i = 0; i < 4; i++) {
        int row = r0 + tr * 4 + i;
        #pragma unroll
        for (int j = 0; j < 8; j++)
            g_yt[row * 128 + tc * 8 + sperm(j)] = tf32r(acc[i][j] + tv[j]);
    }
}

// ---------------- kernel 2: scaled norms ----------------
__global__ __launch_bounds__(128) void norm_kernel(const float* __restrict__ X)
{
    const int row = blockIdx.x, which = blockIdx.y;
    float v = which ? g_yt[row * 128 + threadIdx.x]
                    : tf32r(X[row * 128 + threadIdx.x]);
    float s = v * v;
    #pragma unroll
    for (int o = 16; o; o >>= 1) s += __shfl_down_sync(0xFFFFFFFFu, s, o);
    __shared__ float red[4];
    if ((threadIdx.x & 31) == 0) red[threadIdx.x >> 5] = s;
    __syncthreads();
    if (threadIdx.x == 0) {
        float tot = -(red[0] + red[1] + red[2] + red[3]) * NGL2;
        if (which) g_ck[row] = (row < NROWS) ? tot : -1e30f;
        else       g_cq[row] = tot;
    }
}

// ---------------- kernel 3: V transpose [dim][key], keys permuted ----------
__global__ __launch_bounds__(256) void vt_kernel(const float* __restrict__ X)
{
    __shared__ float ts[64 * 133];
    const int tid = threadIdx.x;
    const int j0 = blockIdx.x * 64;

    #pragma unroll
    for (int i = 0; i < 8; i++) {
        int f = tid + i * 256;
        int r = f >> 5, c4 = f & 31;
        int src = j0 + r + 1; if (src > 8191) src = 8191;
        float4 v = ((const float4*)X)[(size_t)src * 32 + c4];
        float* d = &ts[r * 133 + c4 * 4];
        d[0] = v.x; d[1] = v.y; d[2] = v.z; d[3] = v.w;
    }
    __syncthreads();

    const int w = tid >> 5, l = tid & 31;
    #pragma unroll
    for (int db = 0; db < 16; db++) {
        int d = db * 8 + w;
        #pragma unroll
        for (int it = 0; it < 2; it++) {
            int r = it * 32 + l;
            int jst = (r & ~7) | sperm(r & 7);
            g_vt[(size_t)d * 8192 + j0 + jst] = tf32r(ts[r * 133 + d]);
        }
    }
}

// ---------------- kernel 4: flash RBF attention, split-K over 8 planes -----
// grid (128, 8): blockIdx.x = query tile (64 rows), blockIdx.y = key split s
// (key tiles [16s, 16s+16)). Writes unnormalized O to g_op plane s + den to g_dp.
#define SQ 136
#define SVD 72
#define QSO 0
#define KSO(b)  (8704 + (b) * 8704)
#define VSO(b)  (26112 + (b) * 9216)
#define PSO(pb) (44544 + (pb) * 4608)
#define CKO(b)  (53760 + (b) * 64)
#define DNO 53888
#define SMEM_BYTES (54144 * 4)

__global__ __launch_bounds__(512, 1) void attn_kernel(const float* __restrict__ X)
{
    extern __shared__ float sm[];
    const int tid = threadIdx.x;
    const int w = tid >> 5, l = tid & 31;
    const int gid = l >> 2, tig = l & 3;
    const int wm = w >> 2, q = w & 3;
    const int hm = wm >> 1, kv = q >> 1, nq = ((wm & 1) << 1) | (q & 1);
    const int mb = wm * 16;
    const int mb2 = hm * 32;
    const int nb2 = nq * 32;
    const int barid = 1 + hm * 2 + kv;
    const int r0 = blockIdx.x * 64;
    const int sp = blockIdx.y;               // key split 0..7
    const int t0 = sp * 16;                  // first key tile of this split
    const int s0 = ((tig & 1) << 2) | (tig >> 1);

    {
        const float4* X4 = (const float4*)X;
        #pragma unroll
        for (int i = 0; i < 4; i++) {
            int f = tid + i * 512, r = f >> 5, c4 = f & 31;
            float4 qv = X4[(size_t)(r0 + r) * 32 + c4];
            int base = QSO + r * SQ + (c4 >> 1) * 8 + (c4 & 1);
            sm[base + 0] = tf32r(qv.x); sm[base + 2] = tf32r(qv.y);
            sm[base + 4] = tf32r(qv.z); sm[base + 6] = tf32r(qv.w);
        }
    }
    const float cq0 = g_cq[r0 + mb + gid];
    const float cq1 = g_cq[r0 + mb + gid + 8];

    // prime first tile of this split -> buf 0
    {
        const int j0 = t0 * 64;
        #pragma unroll
        for (int i = 0; i < 4; i++) {
            int f = tid + i * 512, r = f >> 5, c4 = f & 31;
            CP16(smaddr(&sm[KSO(0) + r * SQ + c4 * 4]),
                 g_yt + (size_t)(j0 + r) * 128 + c4 * 4);
        }
        #pragma unroll
        for (int i = 0; i < 4; i++) {
            int f = tid + i * 512, d = f >> 4, c = f & 15;
            CP16(smaddr(&sm[VSO(0) + d * SVD + c * 4]),
                 g_vt + (size_t)d * 8192 + j0 + c * 4);
        }
        if (tid < 16) CP16(smaddr(&sm[CKO(0) + tid * 4]), g_ck + j0 + tid * 4);
        CP_COMMIT();
    }

    float oa[2][4][4];
    #pragma unroll
    for (int m = 0; m < 2; m++)
        #pragma unroll
        for (int n = 0; n < 4; n++)
            #pragma unroll
            for (int j = 0; j < 4; j++) oa[m][n][j] = 0.0f;
    float dn0 = 0.0f, dn1 = 0.0f;

    const int qA0 = (mb + gid) * SQ + 2 * tig;
    const int qA1 = (mb + gid + 8) * SQ + 2 * tig;
    const int kB0 = (q * 16 + gid) * SQ + 2 * tig;
    const int pA0 = (mb2 + gid) * SVD;
    const int vB0 = (nb2 + gid) * SVD;

    #pragma unroll 1
    for (int tt = 0; tt < 16; tt++) {
        const int b = tt & 1;

        CP_WAIT0();
        __syncthreads();

        if (tt + 1 < 16) {
            const int nb = b ^ 1;
            const int j0 = (t0 + tt + 1) * 64;
            #pragma unroll
            for (int i = 0; i < 4; i++) {
                int f = tid + i * 512, r = f >> 5, c4 = f & 31;
                CP16(smaddr(&sm[KSO(nb) + r * SQ + c4 * 4]),
                     g_yt + (size_t)(j0 + r) * 128 + c4 * 4);
            }
            #pragma unroll
            for (int i = 0; i < 4; i++) {
                int f = tid + i * 512, d = f >> 4, c = f & 15;
                CP16(smaddr(&sm[VSO(nb) + d * SVD + c * 4]),
                     g_vt + (size_t)d * 8192 + j0 + c * 4);
            }
            if (tid < 16) CP16(smaddr(&sm[CKO(nb) + tid * 4]), g_ck + j0 + tid * 4);
            CP_COMMIT();
        }

        float sa[2][4];
        #pragma unroll
        for (int n = 0; n < 2; n++)
            #pragma unroll
            for (int j = 0; j < 4; j++) sa[n][j] = 0.0f;

        const uint32_t* QsU = (const uint32_t*)&sm[QSO];
        const uint32_t* KsU = (const uint32_t*)&sm[KSO(b)];
        #pragma unroll
        for (int k0 = 0; k0 < 16; k0++) {
            uint2 aA = *(const uint2*)&QsU[qA0 + k0 * 8];
            uint2 aB = *(const uint2*)&QsU[qA1 + k0 * 8];
            #pragma unroll
            for (int n0 = 0; n0 < 2; n0++) {
                uint2 bb = *(const uint2*)&KsU[kB0 + n0 * 8 * SQ + k0 * 8];
                mma8(sa[n0], aA.x, aB.x, aA.y, aB.y, bb.x, bb.y);
            }
        }

        const float* ckb = &sm[CKO(b)];
        float* Ps = &sm[PSO(b)];
        #pragma unroll
        for (int n0 = 0; n0 < 2; n0++) {
            int cl = q * 16 + n0 * 8;
            float ck0 = ckb[cl + 2 * tig], ck1 = ckb[cl + 2 * tig + 1];
            float p0 = tf32r(ex2f(fmaf(C2, sa[n0][0], cq0 + ck0)));
            float p1 = tf32r(ex2f(fmaf(C2, sa[n0][1], cq0 + ck1)));
            float p2 = tf32r(ex2f(fmaf(C2, sa[n0][2], cq1 + ck0)));
            float p3 = tf32r(ex2f(fmaf(C2, sa[n0][3], cq1 + ck1)));
            dn0 += p0 + p1;
            dn1 += p2 + p3;
            int rA = mb + gid, rB = rA + 8;
            Ps[rA * SVD + cl + s0]     = p0;
            Ps[rA * SVD + cl + s0 + 2] = p1;
            Ps[rB * SVD + cl + s0]     = p2;
            Ps[rB * SVD + cl + s0 + 2] = p3;
        }
        asm volatile("bar.sync %0, %1;" :: "r"(barid), "r"(128) : "memory");

        const uint32_t* PsU = (const uint32_t*)&sm[PSO(b)];
        const uint32_t* VsU = (const uint32_t*)&sm[VSO(b)];
        #pragma unroll
        for (int k0 = 0; k0 < 4; k0++) {
            int kc = kv * 32 + k0 * 8 + 2 * tig;
            uint2 p0 = *(const uint2*)&PsU[pA0 + kc];
            uint2 p1 = *(const uint2*)&PsU[pA0 + 8 * SVD + kc];
            uint2 p2 = *(const uint2*)&PsU[pA0 + 16 * SVD + kc];
            uint2 p3 = *(const uint2*)&PsU[pA0 + 24 * SVD + kc];
            #pragma unroll
            for (int n0 = 0; n0 < 4; n0++) {
                uint2 vb = *(const uint2*)&VsU[vB0 + n0 * 8 * SVD + kc];
                mma8(oa[0][n0], p0.x, p1.x, p0.y, p1.y, vb.x, vb.y);
                mma8(oa[1][n0], p2.x, p3.x, p2.y, p3.y, vb.x, vb.y);
            }
        }
    }

    // ---- epilogue: den quarters -> smem; kv=1 warps park partial O ----
    dn0 += __shfl_xor_sync(0xFFFFFFFFu, dn0, 1);
    dn0 += __shfl_xor_sync(0xFFFFFFFFu, dn0, 2);
    dn1 += __shfl_xor_sync(0xFFFFFFFFu, dn1, 1);
    dn1 += __shfl_xor_sync(0xFFFFFFFFu, dn1, 2);
    if (tig == 0) {
        sm[DNO + q * 64 + mb + gid]     = dn0;
        sm[DNO + q * 64 + mb + gid + 8] = dn1;
    }
    if (kv) {
        float* ob = &sm[VSO(0)];
        #pragma unroll
        for (int m = 0; m < 2; m++) {
            int rA = mb2 + gid + 16 * m, rB = rA + 8;
            #pragma unroll
            for (int n0 = 0; n0 < 4; n0++) {
                int col = nb2 + n0 * 8 + 2 * tig;
                *(float2*)&ob[rA * 132 + col] = make_float2(oa[m][n0][0], oa[m][n0][1]);
                *(float2*)&ob[rB * 132 + col] = make_float2(oa[m][n0][2], oa[m][n0][3]);
            }
        }
    }
    __syncthreads();

    if (!kv) {                               // CTA-level sum -> plane sp (unnormalized)
        float* op = g_op + (size_t)sp * (8192 * 128);
        float* dp = g_dp + sp * 8192;
        const float* ob = &sm[VSO(0)];
        #pragma unroll
        for (int m = 0; m < 2; m++) {
            int rA = mb2 + gid + 16 * m, rB = rA + 8;
            float dA = sm[DNO + rA] + sm[DNO + 64 + rA] + sm[DNO + 128 + rA] + sm[DNO + 192 + rA];
            float dB = sm[DNO + rB] + sm[DNO + 64 + rB] + sm[DNO + 128 + rB] + sm[DNO + 192 + rB];
            int gA = r0 + rA, gB = r0 + rB;
            if (tig == 0 && nq == 0) { dp[gA] = dA; dp[gB] = dB; }
            #pragma unroll
            for (int n0 = 0; n0 < 4; n0++) {
                int col = nb2 + n0 * 8 + 2 * tig;
                float2 uA = *(const float2*)&ob[rA * 132 + col];
                float2 uB = *(const float2*)&ob[rB * 132 + col];
                *(float2*)&op[(size_t)gA * 128 + col] =
                    make_float2(oa[m][n0][0] + uA.x, oa[m][n0][1] + uA.y);
                *(float2*)&op[(size_t)gB * 128 + col] =
                    make_float2(oa[m][n0][2] + uB.x, oa[m][n0][3] + uB.y);
            }
        }
    }
}

// ---------------- kernel 5: combine 8 planes + normalize -------------------
__global__ __launch_bounds__(256) void reduce_kernel(float* __restrict__ out)
{
    int f = blockIdx.x * 256 + threadIdx.x;     // float4 index over 8192*32
    int row = f >> 5, c4 = f & 31;
    if (row >= NROWS) return;
    const float4* p0 = (const float4*)g_op;
    float4 o = make_float4(0.f, 0.f, 0.f, 0.f);
    float den = 0.0f;
    #pragma unroll
    for (int s = 0; s < NSPLIT; s++) {
        float4 a = p0[(size_t)s * (8192 * 32) + row * 32 + c4];
        o.x += a.x; o.y += a.y; o.z += a.z; o.w += a.w;
        den += g_dp[s * 8192 + row];
    }
    float inv = 1.0f / den;
    o.x *= inv; o.y *= inv; o.z *= inv; o.w *= inv;
    ((float4*)out)[(size_t)row * 32 + c4] = o;
}

// ---------------- launch ----------------------------------------------------
extern "C" void kernel_launch(void* const* d_in, const int* in_sizes, int n_in,
                              void* d_out, int out_size)
{
    const float* X = (const float*)d_in[0];
    const float* y = (const float*)d_in[1];
    const float* R = (const float*)d_in[3];
    const float* t = (const float*)d_in[4];
    float* out = (float*)d_out;

    cudaFuncSetAttribute(yt_kernel,   cudaFuncAttributeMaxDynamicSharedMemorySize, 102400);
    cudaFuncSetAttribute(attn_kernel, cudaFuncAttributeMaxDynamicSharedMemorySize, SMEM_BYTES);

    yt_kernel<<<128, 256, 102400>>>(y, R, t);
    norm_kernel<<<dim3(8192, 2), 128>>>(X);
    vt_kernel<<<128, 256>>>(X);
    attn_kernel<<<dim3(128, NSPLIT), 512, SMEM_BYTES>>>(X);
    reduce_kernel<<<1024, 256>>>(out);
}